// round 7
// baseline (speedup 1.0000x reference)
#include <cuda_runtime.h>
#include <cuda_bf16.h>
#include <cstdint>
#include <math.h>

#define T_STEPS 200
#define NB      256
#define H       512
#define CIN     128
#define G4      2048

#define BM 64
#define BN 64
#define BK 32
#define LDT 40      // xproj smem row stride (bf16)
#define GST 72

// persistent step kernel tiling
#define PK 64               // K chunk
#define PLDT 72             // padded row stride (bf16) for PK=64
#define NCTA 128

// ---------------- device scratch ----------------
__device__ __nv_bfloat16 g_wih_hi0[G4*CIN], g_wih_lo0[G4*CIN];
__device__ __nv_bfloat16 g_wih_hi1[G4*H],   g_wih_lo1[G4*H];
__device__ __nv_bfloat16 g_whh_hi0[G4*H],   g_whh_lo0[G4*H];
__device__ __nv_bfloat16 g_whh_hi1[G4*H],   g_whh_lo1[G4*H];
__device__ __nv_bfloat16 g_h_hi0[(size_t)T_STEPS*NB*H], g_h_lo0[(size_t)T_STEPS*NB*H];
__device__ __nv_bfloat16 g_h_hi1[(size_t)T_STEPS*NB*H], g_h_lo1[(size_t)T_STEPS*NB*H];
__device__ __nv_bfloat16 g_x_hi[(size_t)T_STEPS*NB*CIN], g_x_lo[(size_t)T_STEPS*NB*CIN];
__device__ float g_xp[(size_t)T_STEPS*NB*G4];
__device__ float g_c0[NB*H], g_c1[NB*H];
__device__ float g_base[NB*H];
__device__ unsigned g_bar_cnt;   // zero-init; returns to 0 after each barrier
__device__ unsigned g_bar_gen;

// ---------------- helpers ----------------
__device__ __forceinline__ uint32_t smem_u32(const void* p) {
    return (uint32_t)__cvta_generic_to_shared(p);
}
__device__ __forceinline__ void ldm_x4(uint32_t& r0, uint32_t& r1, uint32_t& r2, uint32_t& r3,
                                       uint32_t addr) {
    asm volatile("ldmatrix.sync.aligned.m8n8.x4.shared.b16 {%0,%1,%2,%3}, [%4];"
                 : "=r"(r0), "=r"(r1), "=r"(r2), "=r"(r3) : "r"(addr));
}
__device__ __forceinline__ void mma_bf16(float* c, const uint32_t* a, uint32_t b0, uint32_t b1) {
    asm volatile("mma.sync.aligned.m16n8k16.row.col.f32.bf16.bf16.f32 "
                 "{%0,%1,%2,%3}, {%4,%5,%6,%7}, {%8,%9}, {%0,%1,%2,%3};"
                 : "+f"(c[0]), "+f"(c[1]), "+f"(c[2]), "+f"(c[3])
                 : "r"(a[0]), "r"(a[1]), "r"(a[2]), "r"(a[3]), "r"(b0), "r"(b1));
}
__device__ __forceinline__ void cpa16(uint32_t dst, const void* src) {
    asm volatile("cp.async.cg.shared.global [%0], [%1], 16;" :: "r"(dst), "l"(src));
}
__device__ __forceinline__ void cpa_commit() { asm volatile("cp.async.commit_group;"); }
__device__ __forceinline__ float sigf(float x) { return 1.f / (1.f + expf(-x)); }

// ---------------- init ----------------
__global__ void zero_kernel(float* __restrict__ out, int out_size) {
    int i = blockIdx.x * blockDim.x + threadIdx.x;
    int s = gridDim.x * blockDim.x;
    for (int k = i; k < out_size; k += s) out[k] = 0.f;
    for (int k = i; k < NB * H; k += s) { g_c0[k] = 0.f; g_c1[k] = 0.f; }
}

// ---------------- fp32 -> bf16 hi/lo ----------------
__global__ void conv_w(const float* __restrict__ src, int which, int n) {
    int i = blockIdx.x * blockDim.x + threadIdx.x;
    if (i >= n) return;
    float v = src[i];
    __nv_bfloat16 h = __float2bfloat16(v);
    __nv_bfloat16 l = __float2bfloat16(v - __bfloat162float(h));
    switch (which) {
        case 0: g_wih_hi0[i] = h; g_wih_lo0[i] = l; break;
        case 1: g_whh_hi0[i] = h; g_whh_lo0[i] = l; break;
        case 2: g_wih_hi1[i] = h; g_wih_lo1[i] = l; break;
        case 3: g_whh_hi1[i] = h; g_whh_lo1[i] = l; break;
    }
}
__global__ void conv_x(const float* __restrict__ prop) {
    int i = blockIdx.x * blockDim.x + threadIdx.x;
    if (i >= T_STEPS * NB * CIN) return;
    int k = i & (CIN - 1);
    int m = i >> 7;
    int b = m & (NB - 1), t = m >> 8;
    float v = prop[((size_t)b * T_STEPS + t) * CIN + k];
    __nv_bfloat16 h = __float2bfloat16(v);
    g_x_hi[i] = h;
    g_x_lo[i] = __float2bfloat16(v - __bfloat162float(h));
}

// ---------------- xproj GEMM (unchanged from R5) ----------------
__global__ void __launch_bounds__(256) xproj_mma(int K, int layer,
                                                 const float* __restrict__ bih,
                                                 const float* __restrict__ bhh) {
    __shared__ __align__(16) __nv_bfloat16 Ah[BM][LDT], Al[BM][LDT];
    __shared__ __align__(16) __nv_bfloat16 Bh[BM][LDT], Bl[BM][LDT];
    __shared__ float sbias[BN];

    const int tid  = threadIdx.x;
    const int lane = tid & 31;
    const int warp = tid >> 5;
    const int wm = warp >> 2;
    const int wn = warp & 3;

    const int m0 = blockIdx.y * BM;
    const int n0 = blockIdx.x * BN;
    const __nv_bfloat16* Aptr_hi = layer ? g_h_hi0 : g_x_hi;
    const __nv_bfloat16* Aptr_lo = layer ? g_h_lo0 : g_x_lo;
    const __nv_bfloat16* Bptr_hi = layer ? g_wih_hi1 : g_wih_hi0;
    const __nv_bfloat16* Bptr_lo = layer ? g_wih_lo1 : g_wih_lo0;
    if (tid < BN) sbias[tid] = bih[n0 + tid] + bhh[n0 + tid];

    float acc[2][2][4] = {};
    const int lrow = tid >> 2;
    const int lseg = (tid & 3) * 8;
    const int browg = n0 + lrow;

    const uint32_t aAddrBase[2] = {
        smem_u32(&Ah[wm * 32 + (lane & 15)][(lane >> 4) * 8]),
        smem_u32(&Al[wm * 32 + (lane & 15)][(lane >> 4) * 8])
    };
    const uint32_t bAddrBase[2] = {
        smem_u32(&Bh[wn * 16 + ((lane >> 4) << 3) + (lane & 7)][((lane >> 3) & 1) * 8]),
        smem_u32(&Bl[wn * 16 + ((lane >> 4) << 3) + (lane & 7)][((lane >> 3) & 1) * 8])
    };

    for (int c0 = 0; c0 < K; c0 += BK) {
        size_t ga = (size_t)(m0 + lrow) * K + c0 + lseg;
        size_t gb = (size_t)browg * K + c0 + lseg;
        *(uint4*)&Ah[lrow][lseg] = *(const uint4*)(Aptr_hi + ga);
        *(uint4*)&Al[lrow][lseg] = *(const uint4*)(Aptr_lo + ga);
        *(uint4*)&Bh[lrow][lseg] = *(const uint4*)(Bptr_hi + gb);
        *(uint4*)&Bl[lrow][lseg] = *(const uint4*)(Bptr_lo + gb);
        __syncthreads();

        #pragma unroll
        for (int kk = 0; kk < 2; kk++) {
            const uint32_t koff = (uint32_t)(kk * 16 * 2);
            uint32_t a_hi[2][4], a_lo[2][4];
            #pragma unroll
            for (int mt = 0; mt < 2; mt++) {
                ldm_x4(a_hi[mt][0], a_hi[mt][1], a_hi[mt][2], a_hi[mt][3],
                       aAddrBase[0] + mt * 16 * LDT * 2 + koff);
                ldm_x4(a_lo[mt][0], a_lo[mt][1], a_lo[mt][2], a_lo[mt][3],
                       aAddrBase[1] + mt * 16 * LDT * 2 + koff);
            }
            uint32_t b_hi[4], b_lo[4];
            ldm_x4(b_hi[0], b_hi[1], b_hi[2], b_hi[3], bAddrBase[0] + koff);
            ldm_x4(b_lo[0], b_lo[1], b_lo[2], b_lo[3], bAddrBase[1] + koff);
            #pragma unroll
            for (int mt = 0; mt < 2; mt++)
                #pragma unroll
                for (int nt = 0; nt < 2; nt++) {
                    mma_bf16(acc[mt][nt], a_hi[mt], b_hi[nt * 2], b_hi[nt * 2 + 1]);
                    mma_bf16(acc[mt][nt], a_hi[mt], b_lo[nt * 2], b_lo[nt * 2 + 1]);
                    mma_bf16(acc[mt][nt], a_lo[mt], b_hi[nt * 2], b_hi[nt * 2 + 1]);
                }
        }
        __syncthreads();
    }

    #pragma unroll
    for (int mt = 0; mt < 2; mt++) {
        int r = m0 + wm * 32 + mt * 16 + (lane >> 2);
        #pragma unroll
        for (int nt = 0; nt < 2; nt++) {
            int nn = wn * 16 + nt * 8 + (lane & 3) * 2;
            float b0v = sbias[nn], b1v = sbias[nn + 1];
            int n = n0 + nn;
            g_xp[(size_t)r * G4 + n]           = acc[mt][nt][0] + b0v;
            g_xp[(size_t)r * G4 + n + 1]       = acc[mt][nt][1] + b1v;
            g_xp[(size_t)(r + 8) * G4 + n]     = acc[mt][nt][2] + b0v;
            g_xp[(size_t)(r + 8) * G4 + n + 1] = acc[mt][nt][3] + b1v;
        }
    }
}

// ---------------- persistent LSTM recurrence ----------------
// 128 CTAs, one per SM. CTA (jx, by): j0 = jx*16, b0 = by*64.
// Whh slice (64 gate-rows x 512 K, hi+lo) resident in smem; per step stream
// h_prev (64 x 512, hi+lo) via cp.async in PK=64 chunks; grid barrier between steps.
// smem layout (dynamic):
#define OFF_BH 0
#define SZ_B   (8*64*PLDT*2)                 // 73728 bytes per half
#define OFF_BL (OFF_BH + SZ_B)
#define OFF_A  (OFF_BL + SZ_B)               // 147456
#define SZ_AST (64*PLDT*2)                   // one (stage,half) buffer = 9216 B
#define OFF_G  (OFF_A + 4*SZ_AST)            // 184320
#define PSMEM  (OFF_G + 64*GST*4)            // 202752

__global__ void __launch_bounds__(256, 1) lstm_persist(int layer) {
    extern __shared__ char smem[];
    const uint32_t sb = smem_u32(smem);
    const int tid  = threadIdx.x;
    const int lane = tid & 31;
    const int warp = tid >> 5;
    const int wm = warp >> 2;
    const int wn = warp & 3;
    const int j0 = blockIdx.x * 16;
    const int b0 = blockIdx.y * 64;

    const __nv_bfloat16* Whi = layer ? g_whh_hi1 : g_whh_hi0;
    const __nv_bfloat16* Wlo = layer ? g_whh_lo1 : g_whh_lo0;
    __nv_bfloat16* hb_hi = layer ? g_h_hi1 : g_h_hi0;
    __nv_bfloat16* hb_lo = layer ? g_h_lo1 : g_h_lo0;
    float* cst = layer ? g_c1 : g_c0;

    __nv_bfloat16* Bh_s = (__nv_bfloat16*)(smem + OFF_BH);   // [8][64][PLDT]
    __nv_bfloat16* Bl_s = (__nv_bfloat16*)(smem + OFF_BL);
    float* gst = (float*)(smem + OFF_G);                     // [64][GST]

    // ---- load resident Whh slice (one-time) ----
    for (int idx = tid; idx < 64 * 64; idx += 256) {         // 4096 x 8-elem segs
        int r = idx >> 6, seg = idx & 63;
        int c = seg >> 3, kin = (seg & 7) * 8;
        int wrow = (r >> 4) * H + j0 + (r & 15);
        size_t go = (size_t)wrow * H + seg * 8;
        size_t so = ((size_t)c * 64 + r) * PLDT + kin;
        *(uint4*)(Bh_s + so) = *(const uint4*)(Whi + go);
        *(uint4*)(Bl_s + so) = *(const uint4*)(Wlo + go);
    }
    __syncthreads();

    // per-thread cp.async mapping for A chunks (4 x 16B per thread)
    // idx = tid + i*256: half = idx>>9, r = (idx>>3)&63, seg = idx&7
    // ldmatrix bases
    const int arow = wm * 32 + (lane & 15);
    const int acol = (lane >> 4) * 8;
    const int brow = wn * 16 + ((lane >> 4) << 3) + (lane & 7);
    const int bcol = ((lane >> 3) & 1) * 8;

    for (int t = 0; t < T_STEPS; t++) {
        float acc[2][2][4] = {};

        if (t > 0) {
            const __nv_bfloat16* hp_hi = hb_hi + (size_t)(t - 1) * NB * H;
            const __nv_bfloat16* hp_lo = hb_lo + (size_t)(t - 1) * NB * H;

            // prologue: chunk 0 -> stage 0
            #pragma unroll
            for (int i = 0; i < 4; i++) {
                int idx = tid + i * 256;
                int half = idx >> 9, r = (idx >> 3) & 63, seg = idx & 7;
                const __nv_bfloat16* src = (half ? hp_lo : hp_hi) + (size_t)(b0 + r) * H + seg * 8;
                cpa16(sb + OFF_A + (uint32_t)(half * SZ_AST + (r * PLDT + seg * 8) * 2), src);
            }
            cpa_commit();

            for (int c = 0; c < 8; c++) {
                int st = c & 1;
                if (c < 7) {
                    int ns = (c + 1) & 1;
                    #pragma unroll
                    for (int i = 0; i < 4; i++) {
                        int idx = tid + i * 256;
                        int half = idx >> 9, r = (idx >> 3) & 63, seg = idx & 7;
                        const __nv_bfloat16* src = (half ? hp_lo : hp_hi)
                            + (size_t)(b0 + r) * H + (c + 1) * PK + seg * 8;
                        cpa16(sb + OFF_A + (uint32_t)((ns * 2 + half) * SZ_AST + (r * PLDT + seg * 8) * 2), src);
                    }
                    cpa_commit();
                    asm volatile("cp.async.wait_group 1;");
                } else {
                    asm volatile("cp.async.wait_group 0;");
                }
                __syncthreads();

                const uint32_t aBase[2] = {
                    sb + OFF_A + (uint32_t)((st * 2 + 0) * SZ_AST + (arow * PLDT + acol) * 2),
                    sb + OFF_A + (uint32_t)((st * 2 + 1) * SZ_AST + (arow * PLDT + acol) * 2)
                };
                const uint32_t bBaseH = sb + OFF_BH + (uint32_t)(((c * 64 + brow) * PLDT + bcol) * 2);
                const uint32_t bBaseL = sb + OFF_BL + (uint32_t)(((c * 64 + brow) * PLDT + bcol) * 2);

                #pragma unroll
                for (int kk = 0; kk < 4; kk++) {
                    const uint32_t koff = (uint32_t)(kk * 32);
                    uint32_t a_hi[2][4], a_lo[2][4];
                    #pragma unroll
                    for (int mt = 0; mt < 2; mt++) {
                        ldm_x4(a_hi[mt][0], a_hi[mt][1], a_hi[mt][2], a_hi[mt][3],
                               aBase[0] + mt * 16 * PLDT * 2 + koff);
                        ldm_x4(a_lo[mt][0], a_lo[mt][1], a_lo[mt][2], a_lo[mt][3],
                               aBase[1] + mt * 16 * PLDT * 2 + koff);
                    }
                    uint32_t b_hi[4], b_lo[4];
                    ldm_x4(b_hi[0], b_hi[1], b_hi[2], b_hi[3], bBaseH + koff);
                    ldm_x4(b_lo[0], b_lo[1], b_lo[2], b_lo[3], bBaseL + koff);
                    #pragma unroll
                    for (int mt = 0; mt < 2; mt++)
                        #pragma unroll
                        for (int nt = 0; nt < 2; nt++) {
                            mma_bf16(acc[mt][nt], a_hi[mt], b_hi[nt * 2], b_hi[nt * 2 + 1]);
                            mma_bf16(acc[mt][nt], a_hi[mt], b_lo[nt * 2], b_lo[nt * 2 + 1]);
                            mma_bf16(acc[mt][nt], a_lo[mt], b_hi[nt * 2], b_hi[nt * 2 + 1]);
                        }
                }
                __syncthreads();
            }
        }

        // ---- stage gates ----
        #pragma unroll
        for (int mt = 0; mt < 2; mt++) {
            int r = wm * 32 + mt * 16 + (lane >> 2);
            #pragma unroll
            for (int nt = 0; nt < 2; nt++) {
                int cc = wn * 16 + nt * 8 + (lane & 3) * 2;
                gst[r * GST + cc]           = acc[mt][nt][0];
                gst[r * GST + cc + 1]       = acc[mt][nt][1];
                gst[(r + 8) * GST + cc]     = acc[mt][nt][2];
                gst[(r + 8) * GST + cc + 1] = acc[mt][nt][3];
            }
        }
        __syncthreads();

        // ---- fused cell update ----
        {
            __nv_bfloat16* ho_hi = hb_hi + (size_t)t * NB * H;
            __nv_bfloat16* ho_lo = hb_lo + (size_t)t * NB * H;
            const float* xp = g_xp + (size_t)t * NB * G4;
            const bool wbase = (layer == 1) && (t == T_STEPS - 1);
            #pragma unroll
            for (int i = 0; i < 4; i++) {
                int p  = tid + i * 256;
                int bb = p >> 4, jj = p & 15;
                int b  = b0 + bb;
                const float* xr = xp + (size_t)b * G4 + j0 + jj;
                float gi = gst[bb * GST + jj]      + xr[0 * H];
                float gf = gst[bb * GST + 16 + jj] + xr[1 * H];
                float gg = gst[bb * GST + 32 + jj] + xr[2 * H];
                float go = gst[bb * GST + 48 + jj] + xr[3 * H];
                float iv = sigf(gi), fv = sigf(gf), gv = tanhf(gg), ov = sigf(go);
                size_t idx = (size_t)b * H + j0 + jj;
                float cn = fv * cst[idx] + iv * gv;
                cst[idx] = cn;
                float hv = ov * tanhf(cn);
                __nv_bfloat16 hh = __float2bfloat16(hv);
                ho_hi[idx] = hh;
                ho_lo[idx] = __float2bfloat16(hv - __bfloat162float(hh));
                if (wbase) g_base[idx] = hv;
            }
        }

        // ---- grid barrier (skip after last step) ----
        if (t < T_STEPS - 1) {
            __syncthreads();
            if (tid == 0) {
                __threadfence();
                unsigned my = *(volatile unsigned*)&g_bar_gen;
                unsigned a = atomicAdd(&g_bar_cnt, 1u);
                if (a == NCTA - 1) {
                    g_bar_cnt = 0;
                    __threadfence();
                    atomicAdd(&g_bar_gen, 1u);
                } else {
                    while (*(volatile unsigned*)&g_bar_gen == my) {}
                    __threadfence();
                }
            }
            __syncthreads();
        }
    }
}

// ---------------- heads ----------------
__global__ void heads_kernel(const float* __restrict__ cls_W, const float* __restrict__ cls_b,
                             const float* __restrict__ bbox_W, const float* __restrict__ bbox_b,
                             float* __restrict__ out) {
    __shared__ float base[H];
    int b = blockIdx.x;
    const float* src = g_base + (size_t)b * H;
    for (int k = threadIdx.x; k < H; k += blockDim.x) base[k] = src[k];
    __syncthreads();
    for (int o = threadIdx.x; o < 42; o += blockDim.x) {
        const float* w = (o < 40) ? &cls_W[o * H] : &bbox_W[(o - 40) * H];
        float s = (o < 40) ? cls_b[o] : bbox_b[o - 40];
        #pragma unroll 8
        for (int k = 0; k < H; k++) s += base[k] * w[k];
        if (o < 40) out[b * 40 + o] = s;
        else        out[NB * 40 + b * 2 + (o - 40)] = s;
    }
}

extern "C" void kernel_launch(void* const* d_in, const int* in_sizes, int n_in,
                              void* d_out, int out_size) {
    const float* proposals = (const float*)d_in[2];
    const float* Wih0 = (const float*)d_in[4];
    const float* Whh0 = (const float*)d_in[5];
    const float* bih0 = (const float*)d_in[6];
    const float* bhh0 = (const float*)d_in[7];
    const float* Wih1 = (const float*)d_in[8];
    const float* Whh1 = (const float*)d_in[9];
    const float* bih1 = (const float*)d_in[10];
    const float* bhh1 = (const float*)d_in[11];
    const float* cls_W  = (const float*)d_in[12];
    const float* cls_b  = (const float*)d_in[13];
    const float* bbox_W = (const float*)d_in[14];
    const float* bbox_b = (const float*)d_in[15];
    float* out = (float*)d_out;

    cudaFuncSetAttribute(lstm_persist, cudaFuncAttributeMaxDynamicSharedMemorySize, PSMEM);

    zero_kernel<<<256, 256>>>(out, out_size);

    conv_w<<<(G4 * CIN + 255) / 256, 256>>>(Wih0, 0, G4 * CIN);
    conv_w<<<(G4 * H + 255) / 256, 256>>>(Whh0, 1, G4 * H);
    conv_w<<<(G4 * H + 255) / 256, 256>>>(Wih1, 2, G4 * H);
    conv_w<<<(G4 * H + 255) / 256, 256>>>(Whh1, 3, G4 * H);
    conv_x<<<(T_STEPS * NB * CIN + 255) / 256, 256>>>(proposals);

    dim3 gx(G4 / BN, (T_STEPS * NB) / BM);   // (32, 800)
    dim3 gp(H / 16, NB / 64);                // (32, 4) = 128 CTAs

    xproj_mma<<<gx, 256>>>(CIN, 0, bih0, bhh0);
    lstm_persist<<<gp, 256, PSMEM>>>(0);

    xproj_mma<<<gx, 256>>>(H, 1, bih1, bhh1);
    lstm_persist<<<gp, 256, PSMEM>>>(1);

    heads_kernel<<<NB, 64>>>(cls_W, cls_b, bbox_W, bbox_b, out);
}

// round 8
// speedup vs baseline: 1.4818x; 1.4818x over previous
#include <cuda_runtime.h>
#include <cuda_bf16.h>
#include <cstdint>
#include <math.h>

#define T_STEPS 200
#define NB      256
#define H       512
#define CIN     128
#define G4      2048

// xproj tiling: 128x64, BK=32
#define XBM 128
#define XBN 64
// step tiling: 64(batch) x 64(gate rows), BK=32
#define SBM 64
#define LDT 40          // smem row stride (bf16 elems), 80B
#define GST 72

// dynamic smem offsets (bytes)
// step kernel: A stage-half = 64*40*2 = 5120
#define S_A(s,h)  (((s)*2+(h))*5120)
#define S_B(s,h)  (20480 + ((s)*2+(h))*5120)
#define S_G       40960
#define SSM_TOTAL (40960 + 64*GST*4)        // 59392
// xproj kernel: A stage-half = 128*40*2 = 10240, B stage-half = 5120
#define X_A(s,h)  (((s)*2+(h))*10240)
#define X_B(s,h)  (40960 + ((s)*2+(h))*5120)
#define XSM_TOTAL 61440

// ---------------- device scratch ----------------
__device__ __nv_bfloat16 g_wih_hi0[G4*CIN], g_wih_lo0[G4*CIN];
__device__ __nv_bfloat16 g_wih_hi1[G4*H],   g_wih_lo1[G4*H];
__device__ __nv_bfloat16 g_whh_hi0[G4*H],   g_whh_lo0[G4*H];
__device__ __nv_bfloat16 g_whh_hi1[G4*H],   g_whh_lo1[G4*H];
__device__ __nv_bfloat16 g_h_hi0[(size_t)T_STEPS*NB*H], g_h_lo0[(size_t)T_STEPS*NB*H];
__device__ __nv_bfloat16 g_h_hi1[(size_t)T_STEPS*NB*H], g_h_lo1[(size_t)T_STEPS*NB*H];
__device__ __nv_bfloat16 g_x_hi[(size_t)T_STEPS*NB*CIN], g_x_lo[(size_t)T_STEPS*NB*CIN];
__device__ float g_xp[(size_t)T_STEPS*NB*G4];
__device__ float g_c0[NB*H], g_c1[NB*H];
__device__ float g_base[NB*H];

// ---------------- helpers ----------------
__device__ __forceinline__ uint32_t smem_u32(const void* p) {
    return (uint32_t)__cvta_generic_to_shared(p);
}
__device__ __forceinline__ void ldm_x4(uint32_t& r0, uint32_t& r1, uint32_t& r2, uint32_t& r3,
                                       uint32_t addr) {
    asm volatile("ldmatrix.sync.aligned.m8n8.x4.shared.b16 {%0,%1,%2,%3}, [%4];"
                 : "=r"(r0), "=r"(r1), "=r"(r2), "=r"(r3) : "r"(addr));
}
__device__ __forceinline__ void mma_bf16(float* c, const uint32_t* a, uint32_t b0, uint32_t b1) {
    asm volatile("mma.sync.aligned.m16n8k16.row.col.f32.bf16.bf16.f32 "
                 "{%0,%1,%2,%3}, {%4,%5,%6,%7}, {%8,%9}, {%0,%1,%2,%3};"
                 : "+f"(c[0]), "+f"(c[1]), "+f"(c[2]), "+f"(c[3])
                 : "r"(a[0]), "r"(a[1]), "r"(a[2]), "r"(a[3]), "r"(b0), "r"(b1));
}
__device__ __forceinline__ void cpa16(uint32_t dst, const void* src) {
    asm volatile("cp.async.cg.shared.global [%0], [%1], 16;" :: "r"(dst), "l"(src));
}
__device__ __forceinline__ void cpa_commit() { asm volatile("cp.async.commit_group;"); }
__device__ __forceinline__ void cpa_wait0()  { asm volatile("cp.async.wait_group 0;"); }
__device__ __forceinline__ float sigf(float x) { return 1.f / (1.f + expf(-x)); }

// ---------------- init ----------------
__global__ void zero_kernel(float* __restrict__ out, int out_size) {
    int i = blockIdx.x * blockDim.x + threadIdx.x;
    int s = gridDim.x * blockDim.x;
    for (int k = i; k < out_size; k += s) out[k] = 0.f;
    for (int k = i; k < NB * H; k += s) { g_c0[k] = 0.f; g_c1[k] = 0.f; }
}

// ---------------- fp32 -> bf16 hi/lo ----------------
__global__ void conv_w(const float* __restrict__ src, int which, int n) {
    int i = blockIdx.x * blockDim.x + threadIdx.x;
    if (i >= n) return;
    float v = src[i];
    __nv_bfloat16 h = __float2bfloat16(v);
    __nv_bfloat16 l = __float2bfloat16(v - __bfloat162float(h));
    switch (which) {
        case 0: g_wih_hi0[i] = h; g_wih_lo0[i] = l; break;
        case 1: g_whh_hi0[i] = h; g_whh_lo0[i] = l; break;
        case 2: g_wih_hi1[i] = h; g_wih_lo1[i] = l; break;
        case 3: g_whh_hi1[i] = h; g_whh_lo1[i] = l; break;
    }
}
__global__ void conv_x(const float* __restrict__ prop) {
    int i = blockIdx.x * blockDim.x + threadIdx.x;
    if (i >= T_STEPS * NB * CIN) return;
    int k = i & (CIN - 1);
    int m = i >> 7;
    int b = m & (NB - 1), t = m >> 8;
    float v = prop[((size_t)b * T_STEPS + t) * CIN + k];
    __nv_bfloat16 h = __float2bfloat16(v);
    g_x_hi[i] = h;
    g_x_lo[i] = __float2bfloat16(v - __bfloat162float(h));
}

// ---------------- xproj GEMM: 128x64 tile, 2-stage cp.async pipeline --------
__global__ void __launch_bounds__(256) xproj_mma(int K, int layer,
                                                 const float* __restrict__ bih,
                                                 const float* __restrict__ bhh) {
    extern __shared__ char smem[];
    __shared__ float sbias[XBN];
    const uint32_t sb = smem_u32(smem);
    const int tid  = threadIdx.x;
    const int lane = tid & 31;
    const int warp = tid >> 5;
    const int wm = warp & 3;            // 4 m-warps of 32 rows
    const int wn = warp >> 2;           // 2 n-warps of 32 cols

    const int m0 = blockIdx.y * XBM;
    const int n0 = blockIdx.x * XBN;
    const __nv_bfloat16* Aptr_hi = layer ? g_h_hi0 : g_x_hi;
    const __nv_bfloat16* Aptr_lo = layer ? g_h_lo0 : g_x_lo;
    const __nv_bfloat16* Bptr_hi = layer ? g_wih_hi1 : g_wih_hi0;
    const __nv_bfloat16* Bptr_lo = layer ? g_wih_lo1 : g_wih_lo0;
    if (tid < XBN) sbias[tid] = bih[n0 + tid] + bhh[n0 + tid];

    float acc[2][4][4] = {};
    const int NC = K >> 5;

    // load mapping: A 512 segs/half -> 2 per thread; B 256 segs/half -> 1
    const int ar0 = tid >> 1;                       // wrong granularity fix below
    (void)ar0;
    // A: idx = tid + i*256, i<2: r=idx>>2 (0..127), sg=idx&3
    // B: r=tid>>2 (0..63), sg=tid&3
    const int brow_ld = tid >> 2, bseg_ld = (tid & 3) * 8;

    // ldmatrix fragment addresses (offsets within a stage-half)
    const int acol = (lane >> 4) * 8;
    const int arow_f = wm * 32 + (lane & 15);
    const int brow_f = ((lane >> 4) << 3) + (lane & 7);
    const int bcol_f = ((lane >> 3) & 1) * 8;

    // prologue: chunk 0 -> stage 0
    {
        #pragma unroll
        for (int i = 0; i < 2; i++) {
            int idx = tid + i * 256; int r = idx >> 2, sg = (idx & 3) * 8;
            size_t ga = (size_t)(m0 + r) * K + sg;
            uint32_t so = (uint32_t)(r * LDT + sg) * 2;
            cpa16(sb + X_A(0,0) + so, Aptr_hi + ga);
            cpa16(sb + X_A(0,1) + so, Aptr_lo + ga);
        }
        size_t gb = (size_t)(n0 + brow_ld) * K + bseg_ld;
        uint32_t so = (uint32_t)(brow_ld * LDT + bseg_ld) * 2;
        cpa16(sb + X_B(0,0) + so, Bptr_hi + gb);
        cpa16(sb + X_B(0,1) + so, Bptr_lo + gb);
        cpa_commit();
    }

    for (int c = 0; c < NC; c++) {
        const int st = c & 1;
        cpa_wait0();
        __syncthreads();
        if (c + 1 < NC) {
            const int ns = (c + 1) & 1;
            const int c0 = (c + 1) << 5;
            #pragma unroll
            for (int i = 0; i < 2; i++) {
                int idx = tid + i * 256; int r = idx >> 2, sg = (idx & 3) * 8;
                size_t ga = (size_t)(m0 + r) * K + c0 + sg;
                uint32_t so = (uint32_t)(r * LDT + sg) * 2;
                cpa16(sb + X_A(ns,0) + so, Aptr_hi + ga);
                cpa16(sb + X_A(ns,1) + so, Aptr_lo + ga);
            }
            size_t gb = (size_t)(n0 + brow_ld) * K + c0 + bseg_ld;
            uint32_t so = (uint32_t)(brow_ld * LDT + bseg_ld) * 2;
            cpa16(sb + X_B(ns,0) + so, Bptr_hi + gb);
            cpa16(sb + X_B(ns,1) + so, Bptr_lo + gb);
            cpa_commit();
        }

        const uint32_t aH = sb + X_A(st,0) + (uint32_t)(arow_f * LDT + acol) * 2;
        const uint32_t aL = sb + X_A(st,1) + (uint32_t)(arow_f * LDT + acol) * 2;
        const uint32_t bH0 = sb + X_B(st,0) + (uint32_t)((wn * 32 + brow_f) * LDT + bcol_f) * 2;
        const uint32_t bL0 = sb + X_B(st,1) + (uint32_t)((wn * 32 + brow_f) * LDT + bcol_f) * 2;

        #pragma unroll
        for (int kk = 0; kk < 2; kk++) {
            const uint32_t koff = (uint32_t)(kk * 32);
            uint32_t a_hi[2][4], a_lo[2][4];
            #pragma unroll
            for (int mt = 0; mt < 2; mt++) {
                ldm_x4(a_hi[mt][0], a_hi[mt][1], a_hi[mt][2], a_hi[mt][3],
                       aH + mt * 16 * LDT * 2 + koff);
                ldm_x4(a_lo[mt][0], a_lo[mt][1], a_lo[mt][2], a_lo[mt][3],
                       aL + mt * 16 * LDT * 2 + koff);
            }
            uint32_t b_hi[2][4], b_lo[2][4];
            #pragma unroll
            for (int nf2 = 0; nf2 < 2; nf2++) {
                ldm_x4(b_hi[nf2][0], b_hi[nf2][1], b_hi[nf2][2], b_hi[nf2][3],
                       bH0 + nf2 * 16 * LDT * 2 + koff);
                ldm_x4(b_lo[nf2][0], b_lo[nf2][1], b_lo[nf2][2], b_lo[nf2][3],
                       bL0 + nf2 * 16 * LDT * 2 + koff);
            }
            #pragma unroll
            for (int mt = 0; mt < 2; mt++)
                #pragma unroll
                for (int nf = 0; nf < 4; nf++) {
                    int n2 = nf >> 1, rp = (nf & 1) * 2;
                    mma_bf16(acc[mt][nf], a_hi[mt], b_hi[n2][rp], b_hi[n2][rp + 1]);
                    mma_bf16(acc[mt][nf], a_hi[mt], b_lo[n2][rp], b_lo[n2][rp + 1]);
                    mma_bf16(acc[mt][nf], a_lo[mt], b_hi[n2][rp], b_hi[n2][rp + 1]);
                }
        }
    }
    __syncthreads();

    #pragma unroll
    for (int mt = 0; mt < 2; mt++) {
        int r = m0 + wm * 32 + mt * 16 + (lane >> 2);
        #pragma unroll
        for (int nf = 0; nf < 4; nf++) {
            int nn = wn * 32 + nf * 8 + (lane & 3) * 2;
            float b0v = sbias[nn], b1v = sbias[nn + 1];
            int n = n0 + nn;
            g_xp[(size_t)r * G4 + n]           = acc[mt][nf][0] + b0v;
            g_xp[(size_t)r * G4 + n + 1]       = acc[mt][nf][1] + b1v;
            g_xp[(size_t)(r + 8) * G4 + n]     = acc[mt][nf][2] + b0v;
            g_xp[(size_t)(r + 8) * G4 + n + 1] = acc[mt][nf][3] + b1v;
        }
    }
}

// ---------------- fused LSTM step, 2-stage cp.async pipeline ----------------
// grid (32, 4): j0 = bx*16 (64 gate rows), b0 = by*64
__global__ void __launch_bounds__(256) lstm_step_mma(int t, int layer) {
    extern __shared__ char smem[];
    const uint32_t sb = smem_u32(smem);
    const int tid  = threadIdx.x;
    const int lane = tid & 31;
    const int warp = tid >> 5;
    const int wm = warp >> 2;           // 2 m-warps of 32
    const int wn = warp & 3;            // 4 n-warps of 16
    const int j0 = blockIdx.x * 16;
    const int b0 = blockIdx.y * 64;

    __nv_bfloat16* hb_hi = layer ? g_h_hi1 : g_h_hi0;
    __nv_bfloat16* hb_lo = layer ? g_h_lo1 : g_h_lo0;
    const __nv_bfloat16* Whi = layer ? g_whh_hi1 : g_whh_hi0;
    const __nv_bfloat16* Wlo = layer ? g_whh_lo1 : g_whh_lo0;
    float* cst = layer ? g_c1 : g_c0;
    float* gst = (float*)(smem + S_G);

    float acc[2][2][4] = {};

    if (t > 0) {
        const __nv_bfloat16* hp_hi = hb_hi + (size_t)(t - 1) * NB * H;
        const __nv_bfloat16* hp_lo = hb_lo + (size_t)(t - 1) * NB * H;

        const int lrow = tid >> 2;
        const int lseg = (tid & 3) * 8;
        const int browg = (lrow >> 4) * H + j0 + (lrow & 15);

        const int acol = (lane >> 4) * 8;
        const int arow_f = wm * 32 + (lane & 15);
        const int brow_f = wn * 16 + ((lane >> 4) << 3) + (lane & 7);
        const int bcol_f = ((lane >> 3) & 1) * 8;

        // prologue: chunk 0 -> stage 0
        {
            size_t ga = (size_t)(b0 + lrow) * H + lseg;
            size_t gb = (size_t)browg * H + lseg;
            uint32_t so = (uint32_t)(lrow * LDT + lseg) * 2;
            cpa16(sb + S_A(0,0) + so, hp_hi + ga);
            cpa16(sb + S_A(0,1) + so, hp_lo + ga);
            cpa16(sb + S_B(0,0) + so, Whi + gb);
            cpa16(sb + S_B(0,1) + so, Wlo + gb);
            cpa_commit();
        }

        for (int c = 0; c < 16; c++) {
            const int st = c & 1;
            cpa_wait0();
            __syncthreads();
            if (c + 1 < 16) {
                const int ns = (c + 1) & 1;
                const int c0 = (c + 1) << 5;
                size_t ga = (size_t)(b0 + lrow) * H + c0 + lseg;
                size_t gb = (size_t)browg * H + c0 + lseg;
                uint32_t so = (uint32_t)(lrow * LDT + lseg) * 2;
                cpa16(sb + S_A(ns,0) + so, hp_hi + ga);
                cpa16(sb + S_A(ns,1) + so, hp_lo + ga);
                cpa16(sb + S_B(ns,0) + so, Whi + gb);
                cpa16(sb + S_B(ns,1) + so, Wlo + gb);
                cpa_commit();
            }

            const uint32_t aH = sb + S_A(st,0) + (uint32_t)(arow_f * LDT + acol) * 2;
            const uint32_t aL = sb + S_A(st,1) + (uint32_t)(arow_f * LDT + acol) * 2;
            const uint32_t bH = sb + S_B(st,0) + (uint32_t)(brow_f * LDT + bcol_f) * 2;
            const uint32_t bL = sb + S_B(st,1) + (uint32_t)(brow_f * LDT + bcol_f) * 2;

            #pragma unroll
            for (int kk = 0; kk < 2; kk++) {
                const uint32_t koff = (uint32_t)(kk * 32);
                uint32_t a_hi[2][4], a_lo[2][4];
                #pragma unroll
                for (int mt = 0; mt < 2; mt++) {
                    ldm_x4(a_hi[mt][0], a_hi[mt][1], a_hi[mt][2], a_hi[mt][3],
                           aH + mt * 16 * LDT * 2 + koff);
                    ldm_x4(a_lo[mt][0], a_lo[mt][1], a_lo[mt][2], a_lo[mt][3],
                           aL + mt * 16 * LDT * 2 + koff);
                }
                uint32_t b_hi[4], b_lo[4];
                ldm_x4(b_hi[0], b_hi[1], b_hi[2], b_hi[3], bH + koff);
                ldm_x4(b_lo[0], b_lo[1], b_lo[2], b_lo[3], bL + koff);
                #pragma unroll
                for (int mt = 0; mt < 2; mt++)
                    #pragma unroll
                    for (int nt = 0; nt < 2; nt++) {
                        mma_bf16(acc[mt][nt], a_hi[mt], b_hi[nt * 2], b_hi[nt * 2 + 1]);
                        mma_bf16(acc[mt][nt], a_hi[mt], b_lo[nt * 2], b_lo[nt * 2 + 1]);
                        mma_bf16(acc[mt][nt], a_lo[mt], b_hi[nt * 2], b_hi[nt * 2 + 1]);
                    }
            }
        }
    }

    // stage gates
    #pragma unroll
    for (int mt = 0; mt < 2; mt++) {
        int r = wm * 32 + mt * 16 + (lane >> 2);
        #pragma unroll
        for (int nt = 0; nt < 2; nt++) {
            int cc = wn * 16 + nt * 8 + (lane & 3) * 2;
            gst[r * GST + cc]           = acc[mt][nt][0];
            gst[r * GST + cc + 1]       = acc[mt][nt][1];
            gst[(r + 8) * GST + cc]     = acc[mt][nt][2];
            gst[(r + 8) * GST + cc + 1] = acc[mt][nt][3];
        }
    }
    __syncthreads();

    // fused cell update
    {
        __nv_bfloat16* ho_hi = hb_hi + (size_t)t * NB * H;
        __nv_bfloat16* ho_lo = hb_lo + (size_t)t * NB * H;
        const float* xp = g_xp + (size_t)t * NB * G4;
        const bool wbase = (layer == 1) && (t == T_STEPS - 1);
        #pragma unroll
        for (int i = 0; i < 4; i++) {
            int p  = tid + i * 256;
            int bb = p >> 4, jj = p & 15;
            int b  = b0 + bb;
            const float* xr = xp + (size_t)b * G4 + j0 + jj;
            float gi = gst[bb * GST + jj]      + xr[0 * H];
            float gf = gst[bb * GST + 16 + jj] + xr[1 * H];
            float gg = gst[bb * GST + 32 + jj] + xr[2 * H];
            float go = gst[bb * GST + 48 + jj] + xr[3 * H];
            float iv = sigf(gi), fv = sigf(gf), gv = tanhf(gg), ov = sigf(go);
            size_t idx = (size_t)b * H + j0 + jj;
            float cn = fv * cst[idx] + iv * gv;
            cst[idx] = cn;
            float hv = ov * tanhf(cn);
            __nv_bfloat16 hh = __float2bfloat16(hv);
            ho_hi[idx] = hh;
            ho_lo[idx] = __float2bfloat16(hv - __bfloat162float(hh));
            if (wbase) g_base[idx] = hv;
        }
    }
}

// ---------------- heads ----------------
__global__ void heads_kernel(const float* __restrict__ cls_W, const float* __restrict__ cls_b,
                             const float* __restrict__ bbox_W, const float* __restrict__ bbox_b,
                             float* __restrict__ out) {
    __shared__ float base[H];
    int b = blockIdx.x;
    const float* src = g_base + (size_t)b * H;
    for (int k = threadIdx.x; k < H; k += blockDim.x) base[k] = src[k];
    __syncthreads();
    for (int o = threadIdx.x; o < 42; o += blockDim.x) {
        const float* w = (o < 40) ? &cls_W[o * H] : &bbox_W[(o - 40) * H];
        float s = (o < 40) ? cls_b[o] : bbox_b[o - 40];
        #pragma unroll 8
        for (int k = 0; k < H; k++) s += base[k] * w[k];
        if (o < 40) out[b * 40 + o] = s;
        else        out[NB * 40 + b * 2 + (o - 40)] = s;
    }
}

extern "C" void kernel_launch(void* const* d_in, const int* in_sizes, int n_in,
                              void* d_out, int out_size) {
    const float* proposals = (const float*)d_in[2];
    const float* Wih0 = (const float*)d_in[4];
    const float* Whh0 = (const float*)d_in[5];
    const float* bih0 = (const float*)d_in[6];
    const float* bhh0 = (const float*)d_in[7];
    const float* Wih1 = (const float*)d_in[8];
    const float* Whh1 = (const float*)d_in[9];
    const float* bih1 = (const float*)d_in[10];
    const float* bhh1 = (const float*)d_in[11];
    const float* cls_W  = (const float*)d_in[12];
    const float* cls_b  = (const float*)d_in[13];
    const float* bbox_W = (const float*)d_in[14];
    const float* bbox_b = (const float*)d_in[15];
    float* out = (float*)d_out;

    cudaFuncSetAttribute(xproj_mma, cudaFuncAttributeMaxDynamicSharedMemorySize, XSM_TOTAL);
    cudaFuncSetAttribute(lstm_step_mma, cudaFuncAttributeMaxDynamicSharedMemorySize, SSM_TOTAL);

    zero_kernel<<<256, 256>>>(out, out_size);

    conv_w<<<(G4 * CIN + 255) / 256, 256>>>(Wih0, 0, G4 * CIN);
    conv_w<<<(G4 * H + 255) / 256, 256>>>(Whh0, 1, G4 * H);
    conv_w<<<(G4 * H + 255) / 256, 256>>>(Wih1, 2, G4 * H);
    conv_w<<<(G4 * H + 255) / 256, 256>>>(Whh1, 3, G4 * H);
    conv_x<<<(T_STEPS * NB * CIN + 255) / 256, 256>>>(proposals);

    dim3 gx(G4 / XBN, (T_STEPS * NB) / XBM);   // (32, 400)
    dim3 gs(H / 16, NB / SBM);                 // (32, 4)

    xproj_mma<<<gx, 256, XSM_TOTAL>>>(CIN, 0, bih0, bhh0);
    for (int t = 0; t < T_STEPS; t++)
        lstm_step_mma<<<gs, 256, SSM_TOTAL>>>(t, 0);

    xproj_mma<<<gx, 256, XSM_TOTAL>>>(H, 1, bih1, bhh1);
    for (int t = 0; t < T_STEPS; t++)
        lstm_step_mma<<<gs, 256, SSM_TOTAL>>>(t, 1);

    heads_kernel<<<NB, 64>>>(cls_W, cls_b, bbox_W, bbox_b, out);
}